// round 4
// baseline (speedup 1.0000x reference)
#include <cuda_runtime.h>

typedef unsigned long long u64;

#define N_EDGES_CAP 160000
__device__ float g_mix[(size_t)N_EDGES_CAP * 256];

#define TPB_A 128
#define SMEM_FLOATS 25088  // w1(512) + w2(4096) + w3(4096) + w4(16384)

// ---------- packed f32x2 helpers ----------
__device__ __forceinline__ u64 pack2(float a, float b) {
    u64 r; asm("mov.b64 %0, {%1, %2};" : "=l"(r) : "f"(a), "f"(b)); return r;
}
__device__ __forceinline__ u64 bcast2(float a) { return pack2(a, a); }
__device__ __forceinline__ u64 ffma2(u64 a, u64 b, u64 c) {
    u64 d; asm("fma.rn.f32x2 %0, %1, %2, %3;" : "=l"(d) : "l"(a), "l"(b), "l"(c)); return d;
}
__device__ __forceinline__ void unpack2(float& lo, float& hi, u64 v) {
    asm("mov.b64 {%0, %1}, %2;" : "=f"(lo), "=f"(hi) : "l"(v));
}

__device__ __forceinline__ void red4(float* p, float a, float b, float c, float d) {
    asm volatile("red.global.add.v4.f32 [%0], {%1, %2, %3, %4};"
                 :: "l"(p), "f"(a), "f"(b), "f"(c), "f"(d) : "memory");
}

__device__ __forceinline__ float silu(float x) {
    return __fdividef(x, 1.0f + __expf(-x));
}

// Dense NIN->64, single edge, fully unrolled (all activation indices static).
template<int NIN>
__device__ __forceinline__ void dense1(const float* __restrict__ a,
                                       const float* __restrict__ wsh,
                                       float scale, float post, float* __restrict__ o)
{
    #pragma unroll
    for (int jc = 0; jc < 2; jc++) {
        u64 acc[16];
        #pragma unroll
        for (int m = 0; m < 16; m++) acc[m] = 0ull;
        #pragma unroll
        for (int i = 0; i < NIN; i++) {
            u64 h = bcast2(a[i]);
            const ulonglong2* wr = (const ulonglong2*)(wsh + i * 64 + jc * 32);
            #pragma unroll
            for (int m = 0; m < 8; m++) {
                ulonglong2 w = wr[m];
                acc[2*m]   = ffma2(h, w.x, acc[2*m]);
                acc[2*m+1] = ffma2(h, w.y, acc[2*m+1]);
            }
        }
        #pragma unroll
        for (int m = 0; m < 16; m++) {
            float x, y; unpack2(x, y, acc[m]);
            o[jc*32 + 2*m]     = silu(x * scale) * post;
            o[jc*32 + 2*m + 1] = silu(y * scale) * post;
        }
    }
}

// ===================== Kernel A: radial MLP -> mix =====================
__global__ void __launch_bounds__(TPB_A, 2)
mlp_kernel(const float* __restrict__ radial,
           const float* __restrict__ w1, const float* __restrict__ w2,
           const float* __restrict__ w3, const float* __restrict__ w4,
           int n_edges)
{
    extern __shared__ float smem[];
    float* sw1 = smem;           // 512
    float* sw2 = sw1 + 512;      // 4096
    float* sw3 = sw2 + 4096;     // 4096
    float* sw4 = sw3 + 4096;     // 16384

    int e = blockIdx.x * TPB_A + threadIdx.x;

    // start the per-thread input load BEFORE staging sync to bury latency
    float rr[8];
    bool active = (e < n_edges);
    if (active) {
        const float4* rp = (const float4*)(radial + (size_t)e * 8);
        float4 ra = __ldg(rp), rb = __ldg(rp + 1);
        rr[0]=ra.x; rr[1]=ra.y; rr[2]=ra.z; rr[3]=ra.w;
        rr[4]=rb.x; rr[5]=rb.y; rr[6]=rb.z; rr[7]=rb.w;
    }

    {
        float4* d1 = (float4*)sw1; const float4* s1 = (const float4*)w1;
        for (int i = threadIdx.x; i < 128; i += TPB_A) d1[i] = s1[i];
        float4* d2 = (float4*)sw2; const float4* s2 = (const float4*)w2;
        for (int i = threadIdx.x; i < 1024; i += TPB_A) d2[i] = s2[i];
        float4* d3 = (float4*)sw3; const float4* s3 = (const float4*)w3;
        for (int i = threadIdx.x; i < 1024; i += TPB_A) d3[i] = s3[i];
        float4* d4 = (float4*)sw4; const float4* s4 = (const float4*)w4;
        for (int i = threadIdx.x; i < 4096; i += TPB_A) d4[i] = s4[i];
    }
    __syncthreads();

    if (!active) return;

    float ha[64], hb[64];
    dense1<8>(rr, sw1, 0.35355339059327373f, 1.0f, ha);     // layer 1
    dense1<64>(ha, sw2, 0.125f, 1.0f, hb);                  // layer 2
    // layer 3: fold (1/8 w4-norm)*(1/sqrt(16)) = 1/32 into h3
    dense1<64>(hb, sw3, 0.125f, 0.03125f, ha);

    // mix = h3 @ w4  (8 blocks of 32 output cols)
    float* mrow = g_mix + (size_t)e * 256;
    #pragma unroll 1
    for (int blk = 0; blk < 8; blk++) {
        u64 acc[16];
        #pragma unroll
        for (int m = 0; m < 16; m++) acc[m] = 0ull;
        const float* wbase = sw4 + blk * 32;
        #pragma unroll
        for (int i = 0; i < 64; i++) {
            u64 h = bcast2(ha[i]);
            const ulonglong2* wr = (const ulonglong2*)(wbase + i * 256);
            #pragma unroll
            for (int m = 0; m < 8; m++) {
                ulonglong2 w = wr[m];
                acc[2*m]   = ffma2(h, w.x, acc[2*m]);
                acc[2*m+1] = ffma2(h, w.y, acc[2*m+1]);
            }
        }
        float4* mout = (float4*)(mrow + blk * 32);
        #pragma unroll
        for (int m = 0; m < 8; m++) {
            float4 v;
            unpack2(v.x, v.y, acc[2*m]);
            unpack2(v.z, v.w, acc[2*m+1]);
            mout[m] = v;
        }
    }
}

// ===================== Kernel B: tensor product + coalesced scatter =====================
// Position p in [0,1024): irrep regions
//   r0 [0,64)    W=1  t[p]
//   r1 [64,256)  W=3  tbase=64  ybase=0
//   r2 [256,576) W=5  tbase=128 ybase=3
//   r3 [576,1024)W=7  tbase=192 ybase=8
template<int W, int START, int TB, int YB, int MUL>
__device__ __forceinline__ float tpv(const float* tsh, const float* ysh, int p) {
    int pp = p - START;
    int c = (pp * MUL) >> 16;
    int k = pp - c * W;
    return tsh[TB + c] * ysh[YB + k];
}

#define TPB_B 256

__global__ void __launch_bounds__(TPB_B)
scatter_kernel(const float* __restrict__ vectors,
               const float* __restrict__ node_feats,
               const int* __restrict__ senders,
               const int* __restrict__ receivers,
               float* __restrict__ out, int n_edges)
{
    __shared__ float stage[TPB_B / 32][272];   // per-warp: t[256] + y[15]
    int warp = threadIdx.x >> 5, lane = threadIdx.x & 31;
    int e = blockIdx.x * (TPB_B / 32) + warp;
    if (e >= n_edges) return;

    float* tsh = stage[warp];
    float* ysh = tsh + 256;

    int snd = __ldg(senders + e), rcv = __ldg(receivers + e);

    // t[c] = node_feats[snd][c & 63] * mix[e][c], lane covers c = lane*8..+7
    {
        const float4* mp = (const float4*)(g_mix + (size_t)e * 256) + lane * 2;
        float4 m0 = __ldg(mp), m1 = __ldg(mp + 1);
        const float4* sp = (const float4*)(node_feats + (size_t)snd * 64) + (lane & 7) * 2;
        float4 s0 = __ldg(sp), s1 = __ldg(sp + 1);
        float4 t0 = make_float4(m0.x*s0.x, m0.y*s0.y, m0.z*s0.z, m0.w*s0.w);
        float4 t1 = make_float4(m1.x*s1.x, m1.y*s1.y, m1.z*s1.z, m1.w*s1.w);
        ((float4*)tsh)[lane*2]     = t0;
        ((float4*)tsh)[lane*2 + 1] = t1;
    }

    // spherical harmonics (lane 0 stores 15 floats)
    {
        float vx = __ldg(vectors + 3*(size_t)e + 0);
        float vy = __ldg(vectors + 3*(size_t)e + 1);
        float vz = __ldg(vectors + 3*(size_t)e + 2);
        float inv = 1.0f / (sqrtf(vx*vx + vy*vy + vz*vz) + 1e-12f);
        float x = vx*inv, y = vy*inv, z = vz*inv;
        const float s3  = 1.7320508075688772f;
        const float s5  = 2.23606797749979f;
        const float s15 = 3.872983346207417f;
        const float c33 = 2.091650066335189f;
        const float c32 = 10.246950765959598f;
        const float c31 = 1.6201851746019651f;
        const float c30 = 1.3228756555322954f;
        float z2 = z*z, x2 = x*x, y2 = y*y;
        if (lane == 0) {
            ysh[0]  = s3 * y;  ysh[1] = s3 * z;  ysh[2] = s3 * x;
            ysh[3]  = s15 * x * y;
            ysh[4]  = s15 * y * z;
            ysh[5]  = 0.5f * s5 * (3.0f * z2 - 1.0f);
            ysh[6]  = s15 * x * z;
            ysh[7]  = 0.5f * s15 * (x2 - y2);
            ysh[8]  = c33 * y * (3.0f * x2 - y2);
            ysh[9]  = c32 * x * y * z;
            ysh[10] = c31 * y * (5.0f * z2 - 1.0f);
            ysh[11] = c30 * z * (5.0f * z2 - 3.0f);
            ysh[12] = c31 * x * (5.0f * z2 - 1.0f);
            ysh[13] = 0.5f * c32 * z * (x2 - y2);
            ysh[14] = c33 * x * (x2 - 3.0f * y2);
        }
    }
    __syncwarp();

    float* ob = out + (size_t)rcv * 1024;

    #pragma unroll
    for (int j = 0; j < 8; j++) {
        int p0 = j * 128 + lane * 4;
        float v0, v1, v2, v3;
        if (j == 0) {
            if (lane < 16) {  // r0: scalars, y=1
                v0 = tsh[p0]; v1 = tsh[p0+1]; v2 = tsh[p0+2]; v3 = tsh[p0+3];
            } else {          // r1
                v0 = tpv<3,64,64,0,21846>(tsh, ysh, p0);
                v1 = tpv<3,64,64,0,21846>(tsh, ysh, p0+1);
                v2 = tpv<3,64,64,0,21846>(tsh, ysh, p0+2);
                v3 = tpv<3,64,64,0,21846>(tsh, ysh, p0+3);
            }
        } else if (j == 1) {  // r1
            v0 = tpv<3,64,64,0,21846>(tsh, ysh, p0);
            v1 = tpv<3,64,64,0,21846>(tsh, ysh, p0+1);
            v2 = tpv<3,64,64,0,21846>(tsh, ysh, p0+2);
            v3 = tpv<3,64,64,0,21846>(tsh, ysh, p0+3);
        } else if (j == 2 || j == 3) {  // r2
            v0 = tpv<5,256,128,3,13108>(tsh, ysh, p0);
            v1 = tpv<5,256,128,3,13108>(tsh, ysh, p0+1);
            v2 = tpv<5,256,128,3,13108>(tsh, ysh, p0+2);
            v3 = tpv<5,256,128,3,13108>(tsh, ysh, p0+3);
        } else if (j == 4) {
            if (lane < 16) {  // r2 tail
                v0 = tpv<5,256,128,3,13108>(tsh, ysh, p0);
                v1 = tpv<5,256,128,3,13108>(tsh, ysh, p0+1);
                v2 = tpv<5,256,128,3,13108>(tsh, ysh, p0+2);
                v3 = tpv<5,256,128,3,13108>(tsh, ysh, p0+3);
            } else {          // r3 head
                v0 = tpv<7,576,192,8,9363>(tsh, ysh, p0);
                v1 = tpv<7,576,192,8,9363>(tsh, ysh, p0+1);
                v2 = tpv<7,576,192,8,9363>(tsh, ysh, p0+2);
                v3 = tpv<7,576,192,8,9363>(tsh, ysh, p0+3);
            }
        } else {              // r3
            v0 = tpv<7,576,192,8,9363>(tsh, ysh, p0);
            v1 = tpv<7,576,192,8,9363>(tsh, ysh, p0+1);
            v2 = tpv<7,576,192,8,9363>(tsh, ysh, p0+2);
            v3 = tpv<7,576,192,8,9363>(tsh, ysh, p0+3);
        }
        red4(ob + p0, v0, v1, v2, v3);
    }
}

extern "C" void kernel_launch(void* const* d_in, const int* in_sizes, int n_in,
                              void* d_out, int out_size)
{
    const float* vectors    = (const float*)d_in[0];
    const float* node_feats = (const float*)d_in[1];
    const float* radial     = (const float*)d_in[2];
    const float* w1         = (const float*)d_in[3];
    const float* w2         = (const float*)d_in[4];
    const float* w3         = (const float*)d_in[5];
    const float* w4         = (const float*)d_in[6];
    const int*   senders    = (const int*)d_in[7];
    const int*   receivers  = (const int*)d_in[8];
    float* out = (float*)d_out;

    int n_edges = in_sizes[7];

    cudaFuncSetAttribute(mlp_kernel,
                         cudaFuncAttributeMaxDynamicSharedMemorySize,
                         SMEM_FLOATS * sizeof(float));

    cudaMemsetAsync(d_out, 0, (size_t)out_size * sizeof(float));

    int grid_a = (n_edges + TPB_A - 1) / TPB_A;
    mlp_kernel<<<grid_a, TPB_A, SMEM_FLOATS * sizeof(float)>>>(
        radial, w1, w2, w3, w4, n_edges);

    int edges_per_blk = TPB_B / 32;
    int grid_b = (n_edges + edges_per_blk - 1) / edges_per_blk;
    scatter_kernel<<<grid_b, TPB_B>>>(vectors, node_feats, senders, receivers,
                                      out, n_edges);
}

// round 5
// speedup vs baseline: 1.0666x; 1.0666x over previous
#include <cuda_runtime.h>

typedef unsigned long long u64;

#define N_EDGES_CAP 160000
__device__ float g_mix[(size_t)N_EDGES_CAP * 256];

#define TPB_A 128
#define SMEM_FLOATS 25088  // w1(512) + w2(4096) + w3(4096) + w4(16384)

// ---------- packed f32x2 helpers ----------
__device__ __forceinline__ u64 pack2(float a, float b) {
    u64 r; asm("mov.b64 %0, {%1, %2};" : "=l"(r) : "f"(a), "f"(b)); return r;
}
__device__ __forceinline__ u64 bcast2(float a) { return pack2(a, a); }
__device__ __forceinline__ u64 ffma2(u64 a, u64 b, u64 c) {
    u64 d; asm("fma.rn.f32x2 %0, %1, %2, %3;" : "=l"(d) : "l"(a), "l"(b), "l"(c)); return d;
}
__device__ __forceinline__ void unpack2(float& lo, float& hi, u64 v) {
    asm("mov.b64 {%0, %1}, %2;" : "=f"(lo), "=f"(hi) : "l"(v));
}

__device__ __forceinline__ void red4(float* p, float a, float b, float c, float d) {
    asm volatile("red.global.add.v4.f32 [%0], {%1, %2, %3, %4};"
                 :: "l"(p), "f"(a), "f"(b), "f"(c), "f"(d) : "memory");
}

__device__ __forceinline__ float silu(float x) {
    return __fdividef(x, 1.0f + __expf(-x));
}

// Dense NIN->64, single edge, fully unrolled (all activation indices static).
template<int NIN>
__device__ __forceinline__ void dense1(const float* __restrict__ a,
                                       const float* __restrict__ wsh,
                                       float scale, float post, float* __restrict__ o)
{
    #pragma unroll
    for (int jc = 0; jc < 2; jc++) {
        u64 acc[16];
        #pragma unroll
        for (int m = 0; m < 16; m++) acc[m] = 0ull;
        #pragma unroll
        for (int i = 0; i < NIN; i++) {
            u64 h = bcast2(a[i]);
            const ulonglong2* wr = (const ulonglong2*)(wsh + i * 64 + jc * 32);
            #pragma unroll
            for (int m = 0; m < 8; m++) {
                ulonglong2 w = wr[m];
                acc[2*m]   = ffma2(h, w.x, acc[2*m]);
                acc[2*m+1] = ffma2(h, w.y, acc[2*m+1]);
            }
        }
        #pragma unroll
        for (int m = 0; m < 16; m++) {
            float x, y; unpack2(x, y, acc[m]);
            o[jc*32 + 2*m]     = silu(x * scale) * post;
            o[jc*32 + 2*m + 1] = silu(y * scale) * post;
        }
    }
}

// ===================== Kernel A: radial MLP -> mix (2 edges/thread) =====================
__global__ void __launch_bounds__(TPB_A, 2)
mlp_kernel(const float* __restrict__ radial,
           const float* __restrict__ w1, const float* __restrict__ w2,
           const float* __restrict__ w3, const float* __restrict__ w4,
           int n_edges)
{
    extern __shared__ float smem[];
    float* sw1 = smem;           // 512
    float* sw2 = sw1 + 512;      // 4096
    float* sw3 = sw2 + 4096;     // 4096
    float* sw4 = sw3 + 4096;     // 16384

    int e0 = blockIdx.x * (2 * TPB_A) + threadIdx.x;
    int e1 = e0 + TPB_A;
    bool a0 = (e0 < n_edges);
    bool a1 = (e1 < n_edges);
    int ee0 = a0 ? e0 : 0;
    int ee1 = a1 ? e1 : ee0;

    // per-thread inputs loaded BEFORE the staging sync (bury LDG latency)
    float r0[8], r1[8];
    {
        const float4* rp = (const float4*)(radial + (size_t)ee0 * 8);
        float4 ra = __ldg(rp), rb = __ldg(rp + 1);
        r0[0]=ra.x; r0[1]=ra.y; r0[2]=ra.z; r0[3]=ra.w;
        r0[4]=rb.x; r0[5]=rb.y; r0[6]=rb.z; r0[7]=rb.w;
        const float4* rq = (const float4*)(radial + (size_t)ee1 * 8);
        float4 rc = __ldg(rq), rd = __ldg(rq + 1);
        r1[0]=rc.x; r1[1]=rc.y; r1[2]=rc.z; r1[3]=rc.w;
        r1[4]=rd.x; r1[5]=rd.y; r1[6]=rd.z; r1[7]=rd.w;
    }

    {
        float4* d1 = (float4*)sw1; const float4* s1 = (const float4*)w1;
        for (int i = threadIdx.x; i < 128; i += TPB_A) d1[i] = s1[i];
        float4* d2 = (float4*)sw2; const float4* s2 = (const float4*)w2;
        for (int i = threadIdx.x; i < 1024; i += TPB_A) d2[i] = s2[i];
        float4* d3 = (float4*)sw3; const float4* s3 = (const float4*)w3;
        for (int i = threadIdx.x; i < 1024; i += TPB_A) d3[i] = s3[i];
        float4* d4 = (float4*)sw4; const float4* s4 = (const float4*)w4;
        for (int i = threadIdx.x; i < 4096; i += TPB_A) d4[i] = s4[i];
    }
    __syncthreads();

    if (!a0) return;

    // layers 1-3 sequentially per edge (layer-3 folds (1/8)*(1/sqrt16) = 1/32)
    float h3_0[64], h3_1[64];
    {
        float ha[64], hb[64];
        dense1<8>(r0, sw1, 0.35355339059327373f, 1.0f, ha);
        dense1<64>(ha, sw2, 0.125f, 1.0f, hb);
        dense1<64>(hb, sw3, 0.125f, 0.03125f, h3_0);
    }
    {
        float ha[64], hb[64];
        dense1<8>(r1, sw1, 0.35355339059327373f, 1.0f, ha);
        dense1<64>(ha, sw2, 0.125f, 1.0f, hb);
        dense1<64>(hb, sw3, 0.125f, 0.03125f, h3_1);
    }

    // mix = h3 @ w4, both edges sharing each weight load.
    // 16 blocks of 16 output cols: acc footprint 2x8 u64 = 32 regs.
    float* m0 = g_mix + (size_t)e0 * 256;
    float* m1 = g_mix + (size_t)ee1 * 256;
    #pragma unroll 1
    for (int blk = 0; blk < 16; blk++) {
        u64 acc0[8], acc1[8];
        #pragma unroll
        for (int m = 0; m < 8; m++) { acc0[m] = 0ull; acc1[m] = 0ull; }
        const float* wbase = sw4 + blk * 16;
        #pragma unroll
        for (int i = 0; i < 64; i++) {
            u64 ha = bcast2(h3_0[i]);
            u64 hb = bcast2(h3_1[i]);
            const ulonglong2* wr = (const ulonglong2*)(wbase + i * 256);
            ulonglong2 wA = wr[0];
            ulonglong2 wB = wr[1];
            acc0[0] = ffma2(ha, wA.x, acc0[0]);
            acc1[0] = ffma2(hb, wA.x, acc1[0]);
            acc0[1] = ffma2(ha, wA.y, acc0[1]);
            acc1[1] = ffma2(hb, wA.y, acc1[1]);
            acc0[2] = ffma2(ha, wB.x, acc0[2]);
            acc1[2] = ffma2(hb, wB.x, acc1[2]);
            acc0[3] = ffma2(ha, wB.y, acc0[3]);
            acc1[3] = ffma2(hb, wB.y, acc1[3]);
            ulonglong2 wC = wr[2];
            ulonglong2 wD = wr[3];
            acc0[4] = ffma2(ha, wC.x, acc0[4]);
            acc1[4] = ffma2(hb, wC.x, acc1[4]);
            acc0[5] = ffma2(ha, wC.y, acc0[5]);
            acc1[5] = ffma2(hb, wC.y, acc1[5]);
            acc0[6] = ffma2(ha, wD.x, acc0[6]);
            acc1[6] = ffma2(hb, wD.x, acc1[6]);
            acc0[7] = ffma2(ha, wD.y, acc0[7]);
            acc1[7] = ffma2(hb, wD.y, acc1[7]);
        }
        float4* o0 = (float4*)(m0 + blk * 16);
        #pragma unroll
        for (int m = 0; m < 4; m++) {
            float4 v;
            unpack2(v.x, v.y, acc0[2*m]);
            unpack2(v.z, v.w, acc0[2*m+1]);
            o0[m] = v;
        }
        if (a1) {
            float4* o1 = (float4*)(m1 + blk * 16);
            #pragma unroll
            for (int m = 0; m < 4; m++) {
                float4 v;
                unpack2(v.x, v.y, acc1[2*m]);
                unpack2(v.z, v.w, acc1[2*m+1]);
                o1[m] = v;
            }
        }
    }
}

// ===================== Kernel B: tensor product + coalesced scatter =====================
// Position p in [0,1024): irrep regions
//   r0 [0,64)    W=1  t[p]
//   r1 [64,256)  W=3  tbase=64  ybase=0
//   r2 [256,576) W=5  tbase=128 ybase=3
//   r3 [576,1024)W=7  tbase=192 ybase=8
template<int W, int START, int TB, int YB, int MUL>
__device__ __forceinline__ float tpv(const float* tsh, const float* ysh, int p) {
    int pp = p - START;
    int c = (pp * MUL) >> 16;
    int k = pp - c * W;
    return tsh[TB + c] * ysh[YB + k];
}

#define TPB_B 256

__global__ void __launch_bounds__(TPB_B)
scatter_kernel(const float* __restrict__ vectors,
               const float* __restrict__ node_feats,
               const int* __restrict__ senders,
               const int* __restrict__ receivers,
               float* __restrict__ out, int n_edges)
{
    __shared__ float stage[TPB_B / 32][272];   // per-warp: t[256] + y[15]
    int warp = threadIdx.x >> 5, lane = threadIdx.x & 31;
    int e = blockIdx.x * (TPB_B / 32) + warp;
    if (e >= n_edges) return;

    float* tsh = stage[warp];
    float* ysh = tsh + 256;

    int snd = __ldg(senders + e), rcv = __ldg(receivers + e);

    // t[c] = node_feats[snd][c & 63] * mix[e][c], lane covers c = lane*8..+7
    {
        const float4* mp = (const float4*)(g_mix + (size_t)e * 256) + lane * 2;
        float4 m0 = __ldg(mp), m1 = __ldg(mp + 1);
        const float4* sp = (const float4*)(node_feats + (size_t)snd * 64) + (lane & 7) * 2;
        float4 s0 = __ldg(sp), s1 = __ldg(sp + 1);
        float4 t0 = make_float4(m0.x*s0.x, m0.y*s0.y, m0.z*s0.z, m0.w*s0.w);
        float4 t1 = make_float4(m1.x*s1.x, m1.y*s1.y, m1.z*s1.z, m1.w*s1.w);
        ((float4*)tsh)[lane*2]     = t0;
        ((float4*)tsh)[lane*2 + 1] = t1;
    }

    // spherical harmonics (lane 0 stores 15 floats)
    {
        float vx = __ldg(vectors + 3*(size_t)e + 0);
        float vy = __ldg(vectors + 3*(size_t)e + 1);
        float vz = __ldg(vectors + 3*(size_t)e + 2);
        float inv = 1.0f / (sqrtf(vx*vx + vy*vy + vz*vz) + 1e-12f);
        float x = vx*inv, y = vy*inv, z = vz*inv;
        const float s3  = 1.7320508075688772f;
        const float s5  = 2.23606797749979f;
        const float s15 = 3.872983346207417f;
        const float c33 = 2.091650066335189f;
        const float c32 = 10.246950765959598f;
        const float c31 = 1.6201851746019651f;
        const float c30 = 1.3228756555322954f;
        float z2 = z*z, x2 = x*x, y2 = y*y;
        if (lane == 0) {
            ysh[0]  = s3 * y;  ysh[1] = s3 * z;  ysh[2] = s3 * x;
            ysh[3]  = s15 * x * y;
            ysh[4]  = s15 * y * z;
            ysh[5]  = 0.5f * s5 * (3.0f * z2 - 1.0f);
            ysh[6]  = s15 * x * z;
            ysh[7]  = 0.5f * s15 * (x2 - y2);
            ysh[8]  = c33 * y * (3.0f * x2 - y2);
            ysh[9]  = c32 * x * y * z;
            ysh[10] = c31 * y * (5.0f * z2 - 1.0f);
            ysh[11] = c30 * z * (5.0f * z2 - 3.0f);
            ysh[12] = c31 * x * (5.0f * z2 - 1.0f);
            ysh[13] = 0.5f * c32 * z * (x2 - y2);
            ysh[14] = c33 * x * (x2 - 3.0f * y2);
        }
    }
    __syncwarp();

    float* ob = out + (size_t)rcv * 1024;

    #pragma unroll
    for (int j = 0; j < 8; j++) {
        int p0 = j * 128 + lane * 4;
        float v0, v1, v2, v3;
        if (j == 0) {
            if (lane < 16) {  // r0: scalars, y=1
                v0 = tsh[p0]; v1 = tsh[p0+1]; v2 = tsh[p0+2]; v3 = tsh[p0+3];
            } else {          // r1
                v0 = tpv<3,64,64,0,21846>(tsh, ysh, p0);
                v1 = tpv<3,64,64,0,21846>(tsh, ysh, p0+1);
                v2 = tpv<3,64,64,0,21846>(tsh, ysh, p0+2);
                v3 = tpv<3,64,64,0,21846>(tsh, ysh, p0+3);
            }
        } else if (j == 1) {  // r1
            v0 = tpv<3,64,64,0,21846>(tsh, ysh, p0);
            v1 = tpv<3,64,64,0,21846>(tsh, ysh, p0+1);
            v2 = tpv<3,64,64,0,21846>(tsh, ysh, p0+2);
            v3 = tpv<3,64,64,0,21846>(tsh, ysh, p0+3);
        } else if (j == 2 || j == 3) {  // r2
            v0 = tpv<5,256,128,3,13108>(tsh, ysh, p0);
            v1 = tpv<5,256,128,3,13108>(tsh, ysh, p0+1);
            v2 = tpv<5,256,128,3,13108>(tsh, ysh, p0+2);
            v3 = tpv<5,256,128,3,13108>(tsh, ysh, p0+3);
        } else if (j == 4) {
            if (lane < 16) {  // r2 tail
                v0 = tpv<5,256,128,3,13108>(tsh, ysh, p0);
                v1 = tpv<5,256,128,3,13108>(tsh, ysh, p0+1);
                v2 = tpv<5,256,128,3,13108>(tsh, ysh, p0+2);
                v3 = tpv<5,256,128,3,13108>(tsh, ysh, p0+3);
            } else {          // r3 head
                v0 = tpv<7,576,192,8,9363>(tsh, ysh, p0);
                v1 = tpv<7,576,192,8,9363>(tsh, ysh, p0+1);
                v2 = tpv<7,576,192,8,9363>(tsh, ysh, p0+2);
                v3 = tpv<7,576,192,8,9363>(tsh, ysh, p0+3);
            }
        } else {              // r3
            v0 = tpv<7,576,192,8,9363>(tsh, ysh, p0);
            v1 = tpv<7,576,192,8,9363>(tsh, ysh, p0+1);
            v2 = tpv<7,576,192,8,9363>(tsh, ysh, p0+2);
            v3 = tpv<7,576,192,8,9363>(tsh, ysh, p0+3);
        }
        red4(ob + p0, v0, v1, v2, v3);
    }
}

extern "C" void kernel_launch(void* const* d_in, const int* in_sizes, int n_in,
                              void* d_out, int out_size)
{
    const float* vectors    = (const float*)d_in[0];
    const float* node_feats = (const float*)d_in[1];
    const float* radial     = (const float*)d_in[2];
    const float* w1         = (const float*)d_in[3];
    const float* w2         = (const float*)d_in[4];
    const float* w3         = (const float*)d_in[5];
    const float* w4         = (const float*)d_in[6];
    const int*   senders    = (const int*)d_in[7];
    const int*   receivers  = (const int*)d_in[8];
    float* out = (float*)d_out;

    int n_edges = in_sizes[7];

    cudaFuncSetAttribute(mlp_kernel,
                         cudaFuncAttributeMaxDynamicSharedMemorySize,
                         SMEM_FLOATS * sizeof(float));

    cudaMemsetAsync(d_out, 0, (size_t)out_size * sizeof(float));

    int grid_a = (n_edges + 2 * TPB_A - 1) / (2 * TPB_A);
    mlp_kernel<<<grid_a, TPB_A, SMEM_FLOATS * sizeof(float)>>>(
        radial, w1, w2, w3, w4, n_edges);

    int edges_per_blk = TPB_B / 32;
    int grid_b = (n_edges + edges_per_blk - 1) / edges_per_blk;
    scatter_kernel<<<grid_b, TPB_B>>>(vectors, node_feats, senders, receivers,
                                      out, n_edges);
}

// round 6
// speedup vs baseline: 1.5053x; 1.4114x over previous
#include <cuda_runtime.h>

typedef unsigned long long u64;

#define N_EDGES_CAP 160000
__device__ float g_mix[(size_t)N_EDGES_CAP * 256];

#define TE 64          // edges per CTA
#define TPB_A 128
#define SMEM_A_BYTES (12288 * 4)   // sA(4096) + sB(4096) + sW(4096) floats

// ---------- packed f32x2 helpers ----------
__device__ __forceinline__ u64 pack2(float a, float b) {
    u64 r; asm("mov.b64 %0, {%1, %2};" : "=l"(r) : "f"(a), "f"(b)); return r;
}
__device__ __forceinline__ u64 bcast2(float a) { return pack2(a, a); }
__device__ __forceinline__ u64 ffma2(u64 a, u64 b, u64 c) {
    u64 d; asm("fma.rn.f32x2 %0, %1, %2, %3;" : "=l"(d) : "l"(a), "l"(b), "l"(c)); return d;
}
__device__ __forceinline__ void unpack2(float& lo, float& hi, u64 v) {
    asm("mov.b64 {%0, %1}, %2;" : "=f"(lo), "=f"(hi) : "l"(v));
}

__device__ __forceinline__ void red4(float* p, float a, float b, float c, float d) {
    asm volatile("red.global.add.v4.f32 [%0], {%1, %2, %3, %4};"
                 :: "l"(p), "f"(a), "f"(b), "f"(c), "f"(d) : "memory");
}

__device__ __forceinline__ float silu(float x) {
    return __fdividef(x, 1.0f + __expf(-x));
}

// GEMM: C[4 edges][8 cols] += sIn[k][e] * sWt[k][j], K steps.
// acc[ei*4 + jp] holds the (ei, 2 cols) packed pair.
template<int K>
__device__ __forceinline__ void gemm16(const float* __restrict__ sIn,
                                       const float* __restrict__ sWt,
                                       int eoff, int joff, u64 (&acc)[16])
{
    #pragma unroll
    for (int m = 0; m < 16; m++) acc[m] = 0ull;
    #pragma unroll 8
    for (int k = 0; k < K; k++) {
        float4 av = *(const float4*)(sIn + k * 64 + eoff);
        const ulonglong2* bp = (const ulonglong2*)(sWt + k * 64 + joff);
        ulonglong2 b0 = bp[0], b1 = bp[1];
        u64 a0 = bcast2(av.x), a1 = bcast2(av.y), a2 = bcast2(av.z), a3 = bcast2(av.w);
        acc[0]  = ffma2(a0, b0.x, acc[0]);
        acc[1]  = ffma2(a0, b0.y, acc[1]);
        acc[2]  = ffma2(a0, b1.x, acc[2]);
        acc[3]  = ffma2(a0, b1.y, acc[3]);
        acc[4]  = ffma2(a1, b0.x, acc[4]);
        acc[5]  = ffma2(a1, b0.y, acc[5]);
        acc[6]  = ffma2(a1, b1.x, acc[6]);
        acc[7]  = ffma2(a1, b1.y, acc[7]);
        acc[8]  = ffma2(a2, b0.x, acc[8]);
        acc[9]  = ffma2(a2, b0.y, acc[9]);
        acc[10] = ffma2(a2, b1.x, acc[10]);
        acc[11] = ffma2(a2, b1.y, acc[11]);
        acc[12] = ffma2(a3, b0.x, acc[12]);
        acc[13] = ffma2(a3, b0.y, acc[13]);
        acc[14] = ffma2(a3, b1.x, acc[14]);
        acc[15] = ffma2(a3, b1.y, acc[15]);
    }
}

// Epilogue: silu(acc*scale)*post, store TRANSPOSED sOut[j][e] (next layer's A).
__device__ __forceinline__ void silu_store_T(u64 (&acc)[16], float scale, float post,
                                             float* __restrict__ sOut, int eoff, int joff)
{
    float c[4][8];
    #pragma unroll
    for (int ei = 0; ei < 4; ei++)
        #pragma unroll
        for (int jp = 0; jp < 4; jp++)
            unpack2(c[ei][2*jp], c[ei][2*jp+1], acc[ei*4 + jp]);
    #pragma unroll
    for (int ei = 0; ei < 4; ei++)
        #pragma unroll
        for (int jj = 0; jj < 8; jj++)
            c[ei][jj] = silu(c[ei][jj] * scale) * post;
    #pragma unroll
    for (int jj = 0; jj < 8; jj++) {
        float4 v = make_float4(c[0][jj], c[1][jj], c[2][jj], c[3][jj]);
        *(float4*)(sOut + (joff + jj) * 64 + eoff) = v;
    }
}

// Layer-4 epilogue: store untransposed [e][j] into the staging tile.
__device__ __forceinline__ void store_mix(u64 (&acc)[16], float* __restrict__ sOut,
                                          int eoff, int joff)
{
    #pragma unroll
    for (int ei = 0; ei < 4; ei++) {
        float4 v0, v1;
        unpack2(v0.x, v0.y, acc[ei*4 + 0]);
        unpack2(v0.z, v0.w, acc[ei*4 + 1]);
        unpack2(v1.x, v1.y, acc[ei*4 + 2]);
        unpack2(v1.z, v1.w, acc[ei*4 + 3]);
        *(float4*)(sOut + (eoff + ei) * 64 + joff)     = v0;
        *(float4*)(sOut + (eoff + ei) * 64 + joff + 4) = v1;
    }
}

// ===================== Kernel A: tiled-GEMM radial MLP -> mix =====================
__global__ void __launch_bounds__(TPB_A)
mlp_kernel(const float* __restrict__ radial,
           const float* __restrict__ w1, const float* __restrict__ w2,
           const float* __restrict__ w3, const float* __restrict__ w4,
           int n_edges)
{
    extern __shared__ float smem[];
    float* sA = smem;          // 4096 floats
    float* sB = smem + 4096;   // 4096
    float* sW = smem + 8192;   // 4096

    int tid = threadIdx.x;
    int e0 = blockIdx.x * TE;
    int eoff = (tid & 15) * 4;   // 16 e-groups of 4 edges
    int joff = (tid >> 4) * 8;   // 8 j-groups of 8 cols

    // stage radial transposed into sA[k][e] (k<8), zero-fill tail edges
    {
        int e  = tid >> 1;
        int kh = (tid & 1) * 4;
        int ge = e0 + e;
        float4 v = make_float4(0.f, 0.f, 0.f, 0.f);
        if (ge < n_edges) v = *(const float4*)(radial + (size_t)ge * 8 + kh);
        sA[(kh + 0) * 64 + e] = v.x;
        sA[(kh + 1) * 64 + e] = v.y;
        sA[(kh + 2) * 64 + e] = v.z;
        sA[(kh + 3) * 64 + e] = v.w;
    }
    // stage w1 (8x64)
    ((float4*)sW)[tid] = ((const float4*)w1)[tid];
    __syncthreads();

    u64 acc[16];

    // layer 1: K=8, scale 1/sqrt(8)
    gemm16<8>(sA, sW, eoff, joff, acc);
    silu_store_T(acc, 0.35355339059327373f, 1.0f, sB, eoff, joff);
    __syncthreads();

    // layer 2
    #pragma unroll
    for (int i = 0; i < 8; i++)
        ((float4*)sW)[tid + i * TPB_A] = ((const float4*)w2)[tid + i * TPB_A];
    __syncthreads();
    gemm16<64>(sB, sW, eoff, joff, acc);
    silu_store_T(acc, 0.125f, 1.0f, sA, eoff, joff);
    __syncthreads();

    // layer 3: fold (1/8 w4-norm)*(1/sqrt(16)) = 1/32 into h3
    #pragma unroll
    for (int i = 0; i < 8; i++)
        ((float4*)sW)[tid + i * TPB_A] = ((const float4*)w3)[tid + i * TPB_A];
    __syncthreads();
    gemm16<64>(sA, sW, eoff, joff, acc);
    silu_store_T(acc, 0.125f, 0.03125f, sB, eoff, joff);
    __syncthreads();

    // layer 4: mix = h3 @ w4, 4 chunks of 64 output cols; h3 persists in sB
    #pragma unroll 1
    for (int chunk = 0; chunk < 4; chunk++) {
        // stage w4[:, chunk*64 .. +63]  (64 rows x 16 float4)
        #pragma unroll
        for (int i = 0; i < 8; i++) {
            int idx = tid + i * TPB_A;            // 0..1023
            int row = idx >> 4, col = idx & 15;
            ((float4*)sW)[idx] =
                *(const float4*)(w4 + (size_t)row * 256 + chunk * 64 + col * 4);
        }
        __syncthreads();
        gemm16<64>(sB, sW, eoff, joff, acc);
        store_mix(acc, sA, eoff, joff);
        __syncthreads();
        // coalesced copy sA tile -> g_mix
        #pragma unroll
        for (int i = 0; i < 8; i++) {
            int idx = tid + i * TPB_A;            // 0..1023 float4
            int row = idx >> 4, col = idx & 15;
            int ge = e0 + row;
            if (ge < n_edges)
                *(float4*)(g_mix + (size_t)ge * 256 + chunk * 64 + col * 4) =
                    ((float4*)sA)[idx];
        }
    }
}

// ===================== Kernel B: tensor product + coalesced scatter =====================
// Position p in [0,1024): irrep regions
//   r0 [0,64)    W=1  t[p]
//   r1 [64,256)  W=3  tbase=64  ybase=0
//   r2 [256,576) W=5  tbase=128 ybase=3
//   r3 [576,1024)W=7  tbase=192 ybase=8
template<int W, int START, int TB, int YB, int MUL>
__device__ __forceinline__ float tpv(const float* tsh, const float* ysh, int p) {
    int pp = p - START;
    int c = (pp * MUL) >> 16;
    int k = pp - c * W;
    return tsh[TB + c] * ysh[YB + k];
}

#define TPB_B 256

__global__ void __launch_bounds__(TPB_B)
scatter_kernel(const float* __restrict__ vectors,
               const float* __restrict__ node_feats,
               const int* __restrict__ senders,
               const int* __restrict__ receivers,
               float* __restrict__ out, int n_edges)
{
    __shared__ float stage[TPB_B / 32][272];   // per-warp: t[256] + y[15]
    int warp = threadIdx.x >> 5, lane = threadIdx.x & 31;
    int e = blockIdx.x * (TPB_B / 32) + warp;
    if (e >= n_edges) return;

    float* tsh = stage[warp];
    float* ysh = tsh + 256;

    int snd = __ldg(senders + e), rcv = __ldg(receivers + e);

    // t[c] = node_feats[snd][c & 63] * mix[e][c]
    {
        const float4* mp = (const float4*)(g_mix + (size_t)e * 256) + lane * 2;
        float4 m0 = __ldg(mp), m1 = __ldg(mp + 1);
        const float4* sp = (const float4*)(node_feats + (size_t)snd * 64) + (lane & 7) * 2;
        float4 s0 = __ldg(sp), s1 = __ldg(sp + 1);
        float4 t0 = make_float4(m0.x*s0.x, m0.y*s0.y, m0.z*s0.z, m0.w*s0.w);
        float4 t1 = make_float4(m1.x*s1.x, m1.y*s1.y, m1.z*s1.z, m1.w*s1.w);
        ((float4*)tsh)[lane*2]     = t0;
        ((float4*)tsh)[lane*2 + 1] = t1;
    }

    // spherical harmonics (lane 0 stores 15 floats)
    {
        float vx = __ldg(vectors + 3*(size_t)e + 0);
        float vy = __ldg(vectors + 3*(size_t)e + 1);
        float vz = __ldg(vectors + 3*(size_t)e + 2);
        float inv = 1.0f / (sqrtf(vx*vx + vy*vy + vz*vz) + 1e-12f);
        float x = vx*inv, y = vy*inv, z = vz*inv;
        const float s3  = 1.7320508075688772f;
        const float s5  = 2.23606797749979f;
        const float s15 = 3.872983346207417f;
        const float c33 = 2.091650066335189f;
        const float c32 = 10.246950765959598f;
        const float c31 = 1.6201851746019651f;
        const float c30 = 1.3228756555322954f;
        float z2 = z*z, x2 = x*x, y2 = y*y;
        if (lane == 0) {
            ysh[0]  = s3 * y;  ysh[1] = s3 * z;  ysh[2] = s3 * x;
            ysh[3]  = s15 * x * y;
            ysh[4]  = s15 * y * z;
            ysh[5]  = 0.5f * s5 * (3.0f * z2 - 1.0f);
            ysh[6]  = s15 * x * z;
            ysh[7]  = 0.5f * s15 * (x2 - y2);
            ysh[8]  = c33 * y * (3.0f * x2 - y2);
            ysh[9]  = c32 * x * y * z;
            ysh[10] = c31 * y * (5.0f * z2 - 1.0f);
            ysh[11] = c30 * z * (5.0f * z2 - 3.0f);
            ysh[12] = c31 * x * (5.0f * z2 - 1.0f);
            ysh[13] = 0.5f * c32 * z * (x2 - y2);
            ysh[14] = c33 * x * (x2 - 3.0f * y2);
        }
    }
    __syncwarp();

    float* ob = out + (size_t)rcv * 1024;

    #pragma unroll
    for (int j = 0; j < 8; j++) {
        int p0 = j * 128 + lane * 4;
        float v0, v1, v2, v3;
        if (j == 0) {
            if (lane < 16) {  // r0: scalars, y=1
                v0 = tsh[p0]; v1 = tsh[p0+1]; v2 = tsh[p0+2]; v3 = tsh[p0+3];
            } else {          // r1
                v0 = tpv<3,64,64,0,21846>(tsh, ysh, p0);
                v1 = tpv<3,64,64,0,21846>(tsh, ysh, p0+1);
                v2 = tpv<3,64,64,0,21846>(tsh, ysh, p0+2);
                v3 = tpv<3,64,64,0,21846>(tsh, ysh, p0+3);
            }
        } else if (j == 1) {  // r1
            v0 = tpv<3,64,64,0,21846>(tsh, ysh, p0);
            v1 = tpv<3,64,64,0,21846>(tsh, ysh, p0+1);
            v2 = tpv<3,64,64,0,21846>(tsh, ysh, p0+2);
            v3 = tpv<3,64,64,0,21846>(tsh, ysh, p0+3);
        } else if (j == 2 || j == 3) {  // r2
            v0 = tpv<5,256,128,3,13108>(tsh, ysh, p0);
            v1 = tpv<5,256,128,3,13108>(tsh, ysh, p0+1);
            v2 = tpv<5,256,128,3,13108>(tsh, ysh, p0+2);
            v3 = tpv<5,256,128,3,13108>(tsh, ysh, p0+3);
        } else if (j == 4) {
            if (lane < 16) {  // r2 tail
                v0 = tpv<5,256,128,3,13108>(tsh, ysh, p0);
                v1 = tpv<5,256,128,3,13108>(tsh, ysh, p0+1);
                v2 = tpv<5,256,128,3,13108>(tsh, ysh, p0+2);
                v3 = tpv<5,256,128,3,13108>(tsh, ysh, p0+3);
            } else {          // r3 head
                v0 = tpv<7,576,192,8,9363>(tsh, ysh, p0);
                v1 = tpv<7,576,192,8,9363>(tsh, ysh, p0+1);
                v2 = tpv<7,576,192,8,9363>(tsh, ysh, p0+2);
                v3 = tpv<7,576,192,8,9363>(tsh, ysh, p0+3);
            }
        } else {              // r3
            v0 = tpv<7,576,192,8,9363>(tsh, ysh, p0);
            v1 = tpv<7,576,192,8,9363>(tsh, ysh, p0+1);
            v2 = tpv<7,576,192,8,9363>(tsh, ysh, p0+2);
            v3 = tpv<7,576,192,8,9363>(tsh, ysh, p0+3);
        }
        red4(ob + p0, v0, v1, v2, v3);
    }
}

extern "C" void kernel_launch(void* const* d_in, const int* in_sizes, int n_in,
                              void* d_out, int out_size)
{
    const float* vectors    = (const float*)d_in[0];
    const float* node_feats = (const float*)d_in[1];
    const float* radial     = (const float*)d_in[2];
    const float* w1         = (const float*)d_in[3];
    const float* w2         = (const float*)d_in[4];
    const float* w3         = (const float*)d_in[5];
    const float* w4         = (const float*)d_in[6];
    const int*   senders    = (const int*)d_in[7];
    const int*   receivers  = (const int*)d_in[8];
    float* out = (float*)d_out;

    int n_edges = in_sizes[7];

    cudaFuncSetAttribute(mlp_kernel,
                         cudaFuncAttributeMaxDynamicSharedMemorySize,
                         SMEM_A_BYTES);

    cudaMemsetAsync(d_out, 0, (size_t)out_size * sizeof(float));

    int grid_a = (n_edges + TE - 1) / TE;
    mlp_kernel<<<grid_a, TPB_A, SMEM_A_BYTES>>>(radial, w1, w2, w3, w4, n_edges);

    int edges_per_blk = TPB_B / 32;
    int grid_b = (n_edges + edges_per_blk - 1) / edges_per_blk;
    scatter_kernel<<<grid_b, TPB_B>>>(vectors, node_feats, senders, receivers,
                                      out, n_edges);
}